// round 9
// baseline (speedup 1.0000x reference)
#include <cuda_runtime.h>
#include <cuda_fp16.h>
#include <cstdint>

// LightGCN encoder: fixed-stride slot-allocated adjacency + fp16-stored
// propagation buffers (fp32 accumulate). Layers 1-2 full graph; layer 3
// fused into the batch gather. fp16 convert fused into the latency-bound
// fill kernel (hides in idle issue slots). 2 nodes per 8-lane group in the
// layer kernel to cut degree-divergence. D = 64.
// kernel_launch performs ONLY kernel launches (graph-capture rules).
#define D 64
#define SLOTS 80   // fixed adjacency slots per node (max degree << 80)

static constexpr int MAX_NODES = 150016;

// Scratch (no cudaMalloc allowed). fp16 node buffers: hx (=x), h1, h2.
__device__ __half g_hb[3][(size_t)MAX_NODES * D];
__device__ int   g_cursor[MAX_NODES];                   // becomes degree after fill
__device__ uint2 g_adj[(size_t)MAX_NODES * SLOTS];      // packed (src, fp32 w bits)

// ---------------------------------------------------------------------------
// zero cursors (must precede fill)
// ---------------------------------------------------------------------------
__global__ void lgcn_zero(int n_nodes) {
    int t = blockIdx.x * blockDim.x + threadIdx.x;
    if (t < n_nodes) g_cursor[t] = 0;
}

// ---------------------------------------------------------------------------
// fill + convert fused:
//   threads [0, E): self-allocating adjacency fill (latency-bound, issue ~5%)
//   threads [E, E + n_nodes*16): x -> fp16 buffer 0 (streaming; hides in fill)
// ---------------------------------------------------------------------------
__global__ void lgcn_fill_conv(const int* __restrict__ src, const int* __restrict__ dst,
                               const float* __restrict__ w,
                               const float* __restrict__ ue, const float* __restrict__ ie,
                               int E, int n_users, int n_nodes) {
    int t = blockIdx.x * blockDim.x + threadIdx.x;
    if (t < E) {
        int d = __ldg(dst + t);
        int pos = atomicAdd(&g_cursor[d], 1);
        if (pos < SLOTS)
            g_adj[(size_t)d * SLOTS + pos] =
                make_uint2((unsigned)__ldg(src + t), __float_as_uint(__ldg(w + t)));
        return;
    }
    int i = t - E;                            // float4 index over node rows
    int total = n_nodes * (D / 4);
    if (i >= total) return;
    int u_lim = n_users * (D / 4);
    float4 v = (i < u_lim) ? reinterpret_cast<const float4*>(ue)[i]
                           : reinterpret_cast<const float4*>(ie)[i - u_lim];
    __half2 p0 = __floats2half2_rn(v.x, v.y);
    __half2 p1 = __floats2half2_rn(v.z, v.w);
    uint2 o = make_uint2(*reinterpret_cast<unsigned*>(&p0), *reinterpret_cast<unsigned*>(&p1));
    reinterpret_cast<uint2*>(g_hb[0])[i] = o;
}

// ---------------------------------------------------------------------------
// fp16(8) -> fp32 weighted accumulate
// ---------------------------------------------------------------------------
__device__ __forceinline__ void acc8(float* s, uint4 u, float w) {
    const __half2* hp = reinterpret_cast<const __half2*>(&u);
    #pragma unroll
    for (int j = 0; j < 4; j++) {
        float2 f = __half22float2(hp[j]);
        s[2 * j]     += w * f.x;
        s[2 * j + 1] += w * f.y;
    }
}

// ---------------------------------------------------------------------------
// layer: 8 threads per node-pair group; each group handles 2 consecutive
// nodes sequentially (cuts intra-warp degree-divergence from max-of-4 to
// max-of-4-pair-sums). Each lane owns 8 halves (16B) of the row.
// ---------------------------------------------------------------------------
__global__ void __launch_bounds__(256) lgcn_layer(int in_sel, int out_sel, int n_nodes) {
    int t = blockIdx.x * blockDim.x + threadIdx.x;
    int g = t >> 3;
    int node0 = g * 2;
    if (node0 >= n_nodes) return;
    unsigned c = t & 7;                               // 16B chunk within 128B row

    const uint4* __restrict__ hin_c = reinterpret_cast<const uint4*>(g_hb[in_sel]) + c;
    uint4* __restrict__ hout_c = reinterpret_cast<uint4*>(g_hb[out_sel]) + c;

    #pragma unroll
    for (int k = 0; k < 2; k++) {
        int node = node0 + k;
        if (node >= n_nodes) break;

        int deg = __ldg(&g_cursor[node]);
        if (deg > SLOTS) deg = SLOTS;
        const uint2* __restrict__ adj = g_adj + (size_t)node * SLOTS;

        float s[8] = {0.f, 0.f, 0.f, 0.f, 0.f, 0.f, 0.f, 0.f};
        int p = 0;
        for (; p + 4 <= deg; p += 4) {
            uint2 m0 = __ldg(adj + p);
            uint2 m1 = __ldg(adj + p + 1);
            uint2 m2 = __ldg(adj + p + 2);
            uint2 m3 = __ldg(adj + p + 3);
            uint4 v0 = hin_c[m0.x * 8u];
            uint4 v1 = hin_c[m1.x * 8u];
            uint4 v2 = hin_c[m2.x * 8u];
            uint4 v3 = hin_c[m3.x * 8u];
            acc8(s, v0, __uint_as_float(m0.y));
            acc8(s, v1, __uint_as_float(m1.y));
            acc8(s, v2, __uint_as_float(m2.y));
            acc8(s, v3, __uint_as_float(m3.y));
        }
        for (; p < deg; ++p) {
            uint2 m = __ldg(adj + p);
            uint4 v = hin_c[m.x * 8u];
            acc8(s, v, __uint_as_float(m.y));
        }

        // pack 8 fp32 sums -> 8 halves -> 16B store
        uint4 o;
        __half2 q0 = __floats2half2_rn(s[0], s[1]);
        __half2 q1 = __floats2half2_rn(s[2], s[3]);
        __half2 q2 = __floats2half2_rn(s[4], s[5]);
        __half2 q3 = __floats2half2_rn(s[6], s[7]);
        o.x = *reinterpret_cast<unsigned*>(&q0);
        o.y = *reinterpret_cast<unsigned*>(&q1);
        o.z = *reinterpret_cast<unsigned*>(&q2);
        o.w = *reinterpret_cast<unsigned*>(&q3);
        hout_c[(unsigned)node * 8u] = o;
    }
}

// ---------------------------------------------------------------------------
// gather + fused layer 3 (only batch rows need h3):
//   out[r] = 0.25*( x[node] + h1[node] + h2[node] + Σ_j w_j*h2[src_j] )
// 8 threads per output row; each owns 8 floats (32B) of the 256B output row.
// ---------------------------------------------------------------------------
__global__ void lgcn_gather(const float* __restrict__ ue, const float* __restrict__ ie,
                            const int* __restrict__ uid, const int* __restrict__ iid,
                            int batch, int n_users, float* __restrict__ out) {
    int t = blockIdx.x * blockDim.x + threadIdx.x;
    int r = t >> 3;                 // output row in [0, 2*batch)
    if (r >= 2 * batch) return;
    unsigned c = t & 7;             // 8-float chunk

    int node;
    const float* xrow;
    if (r < batch) {
        int u = __ldg(uid + r);
        node = u;
        xrow = ue + (size_t)u * D;
    } else {
        int i = __ldg(iid + (r - batch));
        node = n_users + i;
        xrow = ie + (size_t)i * D;
    }

    // start with x (fp32, exact)
    float s[8];
    float4 xa = reinterpret_cast<const float4*>(xrow)[2 * c];
    float4 xb = reinterpret_cast<const float4*>(xrow)[2 * c + 1];
    s[0] = xa.x; s[1] = xa.y; s[2] = xa.z; s[3] = xa.w;
    s[4] = xb.x; s[5] = xb.y; s[6] = xb.z; s[7] = xb.w;

    // + h1 + h2 at node
    const uint4* __restrict__ h1_c = reinterpret_cast<const uint4*>(g_hb[1]) + c;
    const uint4* __restrict__ h2_c = reinterpret_cast<const uint4*>(g_hb[2]) + c;
    acc8(s, h1_c[(unsigned)node * 8u], 1.0f);
    acc8(s, h2_c[(unsigned)node * 8u], 1.0f);

    // + fused layer 3: Σ w * h2[src]
    int deg = __ldg(&g_cursor[node]);
    if (deg > SLOTS) deg = SLOTS;
    const uint2* __restrict__ adj = g_adj + (size_t)node * SLOTS;
    int p = 0;
    for (; p + 4 <= deg; p += 4) {
        uint2 m0 = __ldg(adj + p);
        uint2 m1 = __ldg(adj + p + 1);
        uint2 m2 = __ldg(adj + p + 2);
        uint2 m3 = __ldg(adj + p + 3);
        uint4 v0 = h2_c[m0.x * 8u];
        uint4 v1 = h2_c[m1.x * 8u];
        uint4 v2 = h2_c[m2.x * 8u];
        uint4 v3 = h2_c[m3.x * 8u];
        acc8(s, v0, __uint_as_float(m0.y));
        acc8(s, v1, __uint_as_float(m1.y));
        acc8(s, v2, __uint_as_float(m2.y));
        acc8(s, v3, __uint_as_float(m3.y));
    }
    for (; p < deg; ++p) {
        uint2 m = __ldg(adj + p);
        uint4 v = h2_c[m.x * 8u];
        acc8(s, v, __uint_as_float(m.y));
    }

    const float sc = 0.25f;  // 1 / (NUM_LAYERS + 1)
    float4 oa = make_float4(sc * s[0], sc * s[1], sc * s[2], sc * s[3]);
    float4 ob = make_float4(sc * s[4], sc * s[5], sc * s[6], sc * s[7]);
    float4* orow = reinterpret_cast<float4*>(out + (size_t)r * D);
    orow[2 * c]     = oa;
    orow[2 * c + 1] = ob;
}

// ---------------------------------------------------------------------------
extern "C" void kernel_launch(void* const* d_in, const int* in_sizes, int n_in,
                              void* d_out, int out_size) {
    const float* ue  = (const float*)d_in[0];   // [n_users, 64]
    const float* ie  = (const float*)d_in[1];   // [n_items, 64]
    const float* ew  = (const float*)d_in[2];   // [E]
    const int*   eix = (const int*)d_in[3];     // [2, E] (int32)
    const int*   uid = (const int*)d_in[4];     // [B]
    const int*   iid = (const int*)d_in[5];     // [B]
    float* out = (float*)d_out;

    const int n_users = in_sizes[0] / D;
    const int n_items = in_sizes[1] / D;
    const int n_nodes = n_users + n_items;
    const int E       = in_sizes[2];
    const int batch   = in_sizes[4];

    const int* src = eix;
    const int* dst = eix + E;

    const int TB = 256;
    const int zero_blocks  = (n_nodes + TB - 1) / TB;
    const int fc_threads   = E + n_nodes * (D / 4);
    const int fc_blocks    = (fc_threads + TB - 1) / TB;
    const int n_groups     = (n_nodes + 1) / 2;
    const int layer_blocks = (n_groups * 8 + TB - 1) / TB;

    // ---- zero cursors ----
    lgcn_zero<<<zero_blocks, TB>>>(n_nodes);

    // ---- adjacency fill + fp16 convert (fused; convert hides in fill) ----
    lgcn_fill_conv<<<fc_blocks, TB>>>(src, dst, ew, ue, ie, E, n_users, n_nodes);

    // ---- layers 1-2 full graph on fp16 buffers ----
    lgcn_layer<<<layer_blocks, TB>>>(0, 1, n_nodes);
    lgcn_layer<<<layer_blocks, TB>>>(1, 2, n_nodes);

    // ---- gather with fused layer 3 (batch rows only) ----
    const int gthreads = 2 * batch * 8;
    lgcn_gather<<<(gthreads + TB - 1) / TB, TB>>>(ue, ie, uid, iid, batch, n_users, out);
}

// round 10
// speedup vs baseline: 1.2627x; 1.2627x over previous
#include <cuda_runtime.h>
#include <cuda_fp16.h>
#include <cstdint>

// LightGCN encoder: fixed-stride slot-allocated adjacency (no histogram /
// prefix pass) + fp16-stored propagation buffers (fp32 accumulate via packed
// fma.rn.f32x2). Layers 1-2 computed for all nodes; layer 3 fused into the
// batch gather. D = 64.
// kernel_launch performs ONLY kernel launches (graph-capture rules).
#define D 64
#define SLOTS 80   // fixed adjacency slots per node (max degree << 80)

static constexpr int MAX_NODES = 150016;

// Scratch (no cudaMalloc allowed). fp16 node buffers: hx (=x), h1, h2.
__device__ __half g_hb[3][(size_t)MAX_NODES * D];
__device__ int   g_cursor[MAX_NODES];                   // becomes degree after fill
__device__ uint2 g_adj[(size_t)MAX_NODES * SLOTS];      // packed (src, fp32 w bits)

// ---------------------------------------------------------------------------
// prep: zero cursors AND convert x -> fp16 buffer 0 (independent work fused)
// ---------------------------------------------------------------------------
__global__ void lgcn_prep(const float* __restrict__ ue, const float* __restrict__ ie,
                          int n_users, int n_nodes) {
    int t = blockIdx.x * blockDim.x + threadIdx.x;
    if (t < n_nodes) {
        g_cursor[t] = 0;
        return;
    }
    int i = t - n_nodes;                      // float4 index over node rows
    int total = n_nodes * (D / 4);
    if (i >= total) return;
    int u_lim = n_users * (D / 4);
    float4 v = (i < u_lim) ? reinterpret_cast<const float4*>(ue)[i]
                           : reinterpret_cast<const float4*>(ie)[i - u_lim];
    __half2 p0 = __floats2half2_rn(v.x, v.y);
    __half2 p1 = __floats2half2_rn(v.z, v.w);
    uint2 o = make_uint2(*reinterpret_cast<unsigned*>(&p0), *reinterpret_cast<unsigned*>(&p1));
    reinterpret_cast<uint2*>(g_hb[0])[i] = o;
}

// ---------------------------------------------------------------------------
// fill: self-allocating adjacency. pos = cursor[dst]++ ; slot = dst*SLOTS+pos.
// cursor[n] ends as degree(n). 1 edge/thread.
// ---------------------------------------------------------------------------
__global__ void csr_fill(const int* __restrict__ src, const int* __restrict__ dst,
                         const float* __restrict__ w, int E) {
    int e = blockIdx.x * blockDim.x + threadIdx.x;
    if (e >= E) return;
    int d = __ldg(dst + e);
    int pos = atomicAdd(&g_cursor[d], 1);
    if (pos < SLOTS)
        g_adj[(size_t)d * SLOTS + pos] =
            make_uint2((unsigned)__ldg(src + e), __float_as_uint(__ldg(w + e)));
}

// ---------------------------------------------------------------------------
// packed f32x2 helpers (sm_103a FFMA2 — reachable only via explicit PTX)
// ---------------------------------------------------------------------------
__device__ __forceinline__ unsigned long long pack2(float a, float b) {
    unsigned long long v;
    asm("mov.b64 %0, {%1, %2};" : "=l"(v) : "f"(a), "f"(b));
    return v;
}
__device__ __forceinline__ float2 unpack2(unsigned long long v) {
    float2 f;
    asm("mov.b64 {%0, %1}, %2;" : "=f"(f.x), "=f"(f.y) : "l"(v));
    return f;
}

// fp16(8) -> packed-fp32 weighted accumulate: s[j] += w2 * cvt(half2_j)
__device__ __forceinline__ void acc8p(unsigned long long* s, uint4 u,
                                      unsigned long long w2) {
    const __half2* hp = reinterpret_cast<const __half2*>(&u);
    #pragma unroll
    for (int j = 0; j < 4; j++) {
        float2 f = __half22float2(hp[j]);
        unsigned long long v = pack2(f.x, f.y);
        asm("fma.rn.f32x2 %0, %1, %2, %0;" : "+l"(s[j]) : "l"(v), "l"(w2));
    }
}

// ---------------------------------------------------------------------------
// layer: 8 threads per node, each owns 8 halves (16B) of the row:
//   out[n] = Σ_{j < deg(n)} w_j * in[src_j]   (f32x2 accumulate, fp16 store)
// ---------------------------------------------------------------------------
__global__ void lgcn_layer(int in_sel, int out_sel, int n_nodes) {
    int t = blockIdx.x * blockDim.x + threadIdx.x;
    int node = t >> 3;
    if (node >= n_nodes) return;
    int c = t & 7;                                    // 16B chunk within 128B row

    const uint4* __restrict__ hin = reinterpret_cast<const uint4*>(g_hb[in_sel]);
    int deg = __ldg(&g_cursor[node]);
    if (deg > SLOTS) deg = SLOTS;
    const uint2* __restrict__ adj = g_adj + (size_t)node * SLOTS;

    unsigned long long s[4] = {0ull, 0ull, 0ull, 0ull};
    int p = 0;
    for (; p + 4 <= deg; p += 4) {
        uint2 m0 = __ldg(adj + p);
        uint2 m1 = __ldg(adj + p + 1);
        uint2 m2 = __ldg(adj + p + 2);
        uint2 m3 = __ldg(adj + p + 3);
        uint4 v0 = hin[(size_t)m0.x * 8 + c];
        uint4 v1 = hin[(size_t)m1.x * 8 + c];
        uint4 v2 = hin[(size_t)m2.x * 8 + c];
        uint4 v3 = hin[(size_t)m3.x * 8 + c];
        float w0 = __uint_as_float(m0.y), w1 = __uint_as_float(m1.y);
        float w2 = __uint_as_float(m2.y), w3 = __uint_as_float(m3.y);
        acc8p(s, v0, pack2(w0, w0));
        acc8p(s, v1, pack2(w1, w1));
        acc8p(s, v2, pack2(w2, w2));
        acc8p(s, v3, pack2(w3, w3));
    }
    for (; p < deg; ++p) {
        uint2 m = __ldg(adj + p);
        uint4 v = hin[(size_t)m.x * 8 + c];
        float w = __uint_as_float(m.y);
        acc8p(s, v, pack2(w, w));
    }

    // unpack 4 packed sums -> 8 halves -> 16B store
    float2 f0 = unpack2(s[0]);
    float2 f1 = unpack2(s[1]);
    float2 f2 = unpack2(s[2]);
    float2 f3 = unpack2(s[3]);
    uint4 o;
    __half2 q0 = __floats2half2_rn(f0.x, f0.y);
    __half2 q1 = __floats2half2_rn(f1.x, f1.y);
    __half2 q2 = __floats2half2_rn(f2.x, f2.y);
    __half2 q3 = __floats2half2_rn(f3.x, f3.y);
    o.x = *reinterpret_cast<unsigned*>(&q0);
    o.y = *reinterpret_cast<unsigned*>(&q1);
    o.z = *reinterpret_cast<unsigned*>(&q2);
    o.w = *reinterpret_cast<unsigned*>(&q3);
    reinterpret_cast<uint4*>(g_hb[out_sel])[(size_t)node * 8 + c] = o;
}

// ---------------------------------------------------------------------------
// gather + fused layer 3 (only batch rows need h3):
//   out[r] = 0.25*( x[node] + h1[node] + h2[node] + Σ_j w_j*h2[src_j] )
// 8 threads per output row; each owns 8 floats (32B) of the 256B output row.
// ---------------------------------------------------------------------------
__global__ void lgcn_gather(const float* __restrict__ ue, const float* __restrict__ ie,
                            const int* __restrict__ uid, const int* __restrict__ iid,
                            int batch, int n_users, float* __restrict__ out) {
    int t = blockIdx.x * blockDim.x + threadIdx.x;
    int r = t >> 3;                 // output row in [0, 2*batch)
    if (r >= 2 * batch) return;
    int c = t & 7;                  // 8-float chunk

    int node;
    const float* xrow;
    if (r < batch) {
        int u = __ldg(uid + r);
        node = u;
        xrow = ue + (size_t)u * D;
    } else {
        int i = __ldg(iid + (r - batch));
        node = n_users + i;
        xrow = ie + (size_t)i * D;
    }

    // start with x (fp32, exact)
    float4 xa = reinterpret_cast<const float4*>(xrow)[2 * c];
    float4 xb = reinterpret_cast<const float4*>(xrow)[2 * c + 1];
    unsigned long long s[4];
    s[0] = pack2(xa.x, xa.y);
    s[1] = pack2(xa.z, xa.w);
    s[2] = pack2(xb.x, xb.y);
    s[3] = pack2(xb.z, xb.w);

    const unsigned long long one2 = pack2(1.0f, 1.0f);

    // + h1 + h2 at node
    const uint4* __restrict__ h1 = reinterpret_cast<const uint4*>(g_hb[1]);
    const uint4* __restrict__ h2 = reinterpret_cast<const uint4*>(g_hb[2]);
    acc8p(s, h1[(size_t)node * 8 + c], one2);
    acc8p(s, h2[(size_t)node * 8 + c], one2);

    // + fused layer 3: Σ w * h2[src]
    int deg = __ldg(&g_cursor[node]);
    if (deg > SLOTS) deg = SLOTS;
    const uint2* __restrict__ adj = g_adj + (size_t)node * SLOTS;
    int p = 0;
    for (; p + 4 <= deg; p += 4) {
        uint2 m0 = __ldg(adj + p);
        uint2 m1 = __ldg(adj + p + 1);
        uint2 m2 = __ldg(adj + p + 2);
        uint2 m3 = __ldg(adj + p + 3);
        uint4 v0 = h2[(size_t)m0.x * 8 + c];
        uint4 v1 = h2[(size_t)m1.x * 8 + c];
        uint4 v2 = h2[(size_t)m2.x * 8 + c];
        uint4 v3 = h2[(size_t)m3.x * 8 + c];
        float w0 = __uint_as_float(m0.y), w1 = __uint_as_float(m1.y);
        float w2 = __uint_as_float(m2.y), w3 = __uint_as_float(m3.y);
        acc8p(s, v0, pack2(w0, w0));
        acc8p(s, v1, pack2(w1, w1));
        acc8p(s, v2, pack2(w2, w2));
        acc8p(s, v3, pack2(w3, w3));
    }
    for (; p < deg; ++p) {
        uint2 m = __ldg(adj + p);
        uint4 v = h2[(size_t)m.x * 8 + c];
        float w = __uint_as_float(m.y);
        acc8p(s, v, pack2(w, w));
    }

    const float sc = 0.25f;  // 1 / (NUM_LAYERS + 1)
    float2 f0 = unpack2(s[0]);
    float2 f1 = unpack2(s[1]);
    float2 f2 = unpack2(s[2]);
    float2 f3 = unpack2(s[3]);
    float4 oa = make_float4(sc * f0.x, sc * f0.y, sc * f1.x, sc * f1.y);
    float4 ob = make_float4(sc * f2.x, sc * f2.y, sc * f3.x, sc * f3.y);
    float4* orow = reinterpret_cast<float4*>(out + (size_t)r * D);
    orow[2 * c]     = oa;
    orow[2 * c + 1] = ob;
}

// ---------------------------------------------------------------------------
extern "C" void kernel_launch(void* const* d_in, const int* in_sizes, int n_in,
                              void* d_out, int out_size) {
    const float* ue  = (const float*)d_in[0];   // [n_users, 64]
    const float* ie  = (const float*)d_in[1];   // [n_items, 64]
    const float* ew  = (const float*)d_in[2];   // [E]
    const int*   eix = (const int*)d_in[3];     // [2, E] (int32)
    const int*   uid = (const int*)d_in[4];     // [B]
    const int*   iid = (const int*)d_in[5];     // [B]
    float* out = (float*)d_out;

    const int n_users = in_sizes[0] / D;
    const int n_items = in_sizes[1] / D;
    const int n_nodes = n_users + n_items;
    const int E       = in_sizes[2];
    const int batch   = in_sizes[4];

    const int* src = eix;
    const int* dst = eix + E;

    const int TB = 256;
    const int prep_threads = n_nodes + n_nodes * (D / 4);
    const int prep_blocks  = (prep_threads + TB - 1) / TB;
    const int edge_blocks  = (E + TB - 1) / TB;
    const int layer_blocks = (n_nodes * 8 + TB - 1) / TB;

    // ---- prep: zero cursors + convert x to fp16 (fused) ----
    lgcn_prep<<<prep_blocks, TB>>>(ue, ie, n_users, n_nodes);

    // ---- adjacency fill (self-allocating slots; cursor ends as degree) ----
    csr_fill<<<edge_blocks, TB>>>(src, dst, ew, E);

    // ---- layers 1-2 full graph on fp16 buffers ----
    lgcn_layer<<<layer_blocks, TB>>>(0, 1, n_nodes);
    lgcn_layer<<<layer_blocks, TB>>>(1, 2, n_nodes);

    // ---- gather with fused layer 3 (batch rows only) ----
    const int gthreads = 2 * batch * 8;
    lgcn_gather<<<(gthreads + TB - 1) / TB, TB>>>(ue, ie, uid, iid, batch, n_users, out);
}